// round 15
// baseline (speedup 1.0000x reference)
#include <cuda_runtime.h>
#include <cuda_bf16.h>

// Problem constants
#define NUM_HEADS 8
#define NUM_G     50
#define NUM_ELEM  100
#define NB        (NUM_ELEM * NUM_ELEM)   // 10000 distinct (src,dst) pairs
#define E_MAX     1000000
#define NREP      8                       // counter replicas per bin
#define RCAP      32                      // slots per replica (8*32 = 256 per bin)
#define BINSZ     (NREP * RCAP)           // 256
#define OVF_MAX   8192
#define NTAPS     12                      // truncated RBF support (see analysis)
#define GS_MAX    (NUM_G - NTAPS)         // 38

// offsets = linspace(0, 12, 50) -> spacing 12/49 ; std = 12/50
#define RBF_DELTA (12.0 / 49.0)
#define INV_DELTA (49.0 / 12.0)
// k = -0.5/std^2 * log2(e)  (so exp() becomes ex2.approx)
#define RBF_K     (-8.680555555555555 * 1.4426950408889634)
// arg(g) = K*d^2 + MSLOPE*g*d + CQUAD*g^2   (used by overflow path)
#define MSLOPE    (-2.0 * RBF_K * RBF_DELTA)
#define CQUAD     (RBF_K * RBF_DELTA * RBF_DELTA)

// ---- f32x2 packed helpers (sm_100+ PTX) -----------------------------------
__device__ __forceinline__ unsigned long long pk2(float x, float y) {
    unsigned long long r;
    asm("mov.b64 %0, {%1, %2};" : "=l"(r) : "f"(x), "f"(y));
    return r;
}
__device__ __forceinline__ void upk2(unsigned long long v, float& x, float& y) {
    asm("mov.b64 {%0, %1}, %2;" : "=f"(x), "=f"(y) : "l"(v));
}
__device__ __forceinline__ unsigned long long fma2(unsigned long long a, unsigned long long b,
                                                   unsigned long long c) {
    unsigned long long d;
    asm("fma.rn.f32x2 %0, %1, %2, %3;" : "=l"(d) : "l"(a), "l"(b), "l"(c));
    return d;
}
__device__ __forceinline__ float ex2(float x) {
    float r;
    asm("ex2.approx.f32 %0, %1;" : "=f"(r) : "f"(x));
    return r;
}

// Scratch (no allocations allowed) -------------------------------------------
// g_cnt8 starts zeroed (device global); k_compute re-zeros its bin each launch.
__device__ int4 g_cnt8[NB * 2];            // 8 replica counters per bin
__device__ int2 g_bins[NB * BINSZ];        // {edge_id, dist_bits} (20 MB)
__device__ int  g_ovf_cnt;
__device__ int  g_ovf[OVF_MAX];

// K1: key + replica rank + direct bucket store, software-pipelined MLP=4 ------
// (FROZEN: measured 22.3-22.7us across rounds 11/13/14)
__global__ __launch_bounds__(256) void k_key_direct(
    const int*   __restrict__ anum,
    const int*   __restrict__ esrc,
    const int*   __restrict__ edst,
    const float* __restrict__ dist,
    int E)
{
    const int S   = gridDim.x * blockDim.x;
    const int idx = blockIdx.x * blockDim.x + threadIdx.x;

    int   e[4], s[4], t[4], as[4], ad[4];
    float dd[4];
    bool  ok[4];

#pragma unroll
    for (int u = 0; u < 4; u++) {
        e[u]  = idx + u * S;
        ok[u] = (e[u] < E);
        if (ok[u]) {
            s[u] = __ldg(esrc + e[u]);
            t[u] = __ldg(edst + e[u]);
        }
    }
#pragma unroll
    for (int u = 0; u < 4; u++) {
        if (ok[u]) {
            as[u] = __ldg(anum + s[u]);
            ad[u] = __ldg(anum + t[u]);
            dd[u] = __ldg(dist + e[u]);
        }
    }
    int pos[4], kk[4];
#pragma unroll
    for (int u = 0; u < 4; u++) {
        if (ok[u]) {
            kk[u] = as[u] * NUM_ELEM + ad[u];
            int r = e[u] & (NREP - 1);
            pos[u] = atomicAdd(&((int*)g_cnt8)[kk[u] * NREP + r], 1);
        }
    }
#pragma unroll
    for (int u = 0; u < 4; u++) {
        if (ok[u]) {
            int r = e[u] & (NREP - 1);
            if (pos[u] < RCAP) {
                g_bins[(kk[u] * NREP + r) * RCAP + pos[u]] =
                    make_int2(e[u], __float_as_int(dd[u]));
            } else {
                int o = atomicAdd(&g_ovf_cnt, 1);
                if (o < OVF_MAX) g_ovf[o] = e[u];
            }
        }
    }
}

// K2: one block per pair (+1 overflow block); truncated 12-tap RBF dot.
// Weights transposed in smem: s_w[g*10 + h] (rows padded to 40B for bank spread)
__global__ __launch_bounds__(128) void k_compute(
    const int*   __restrict__ anum,
    const int*   __restrict__ esrc,
    const int*   __restrict__ edst,
    const float* __restrict__ dist,
    const float* __restrict__ emb,
    float*       __restrict__ out)
{
    int b = blockIdx.x;                          // pair key

    // --- overflow block (normally empty); exact 50-tap path ------------------
    if (b == NB) {
        int n = g_ovf_cnt;
        if (n > OVF_MAX) n = OVF_MAX;
        for (int i = threadIdx.x; i < n; i += 128) {
            int e = g_ovf[i];
            int k = __ldg(anum + __ldg(esrc + e)) * NUM_ELEM
                  + __ldg(anum + __ldg(edst + e));
            float d = __ldg(dist + e);
            const float* W = emb + (size_t)k * (NUM_HEADS * NUM_G);
            float t = (float)RBF_K * d * d;
            float rbf[NUM_G];
#pragma unroll
            for (int g = 0; g < NUM_G; g++)
                rbf[g] = ex2(t + (float)(MSLOPE * g) * d + (float)(CQUAD * g * g));
            for (int h = 0; h < NUM_HEADS; h++) {
                float a = 0.f;
#pragma unroll
                for (int g = 0; g < NUM_G; g++)
                    a = fmaf(__ldg(W + h * NUM_G + g), rbf[g], a);
                out[(size_t)e * NUM_HEADS + h] = a;
            }
        }
        __syncthreads();
        if (threadIdx.x == 0) g_ovf_cnt = 0;     // reset for next launch/replay
        return;
    }

    // --- normal bin block ----------------------------------------------------
    __shared__ unsigned char s_map[BINSZ];            // logical idx -> bin slot
    __shared__ __align__(16) float s_w[NUM_G * 10];   // [g][h] rows padded to 10

    // Broadcast counter loads (all threads)
    int4 ca = g_cnt8[2 * b];
    int4 cb = g_cnt8[2 * b + 1];
    int c0 = min(ca.x, RCAP), c1 = min(ca.y, RCAP);
    int c2 = min(ca.z, RCAP), c3 = min(ca.w, RCAP);
    int c4 = min(cb.x, RCAP), c5 = min(cb.y, RCAP);
    int c6 = min(cb.z, RCAP), c7 = min(cb.w, RCAP);
    int p0 = 0;
    int p1 = p0 + c0, p2 = p1 + c1, p3 = p2 + c2, p4 = p3 + c3;
    int p5 = p4 + c4, p6 = p5 + c5, p7 = p6 + c6;
    int cnt = p7 + c7;
    if (cnt == 0) return;                        // uniform: whole block exits

    // Build logical->slot map: slot idx = q*128+tid, replica = q*4 + (tid>>5)
    {
        int wid = threadIdx.x >> 5;
        int tp  = threadIdx.x & (RCAP - 1);
#pragma unroll
        for (int q = 0; q < 2; q++) {
            int cr, pr;
            if (q == 0) {
                cr = (wid < 2) ? (wid == 0 ? c0 : c1) : (wid == 2 ? c2 : c3);
                pr = (wid < 2) ? (wid == 0 ? p0 : p1) : (wid == 2 ? p2 : p3);
            } else {
                cr = (wid < 2) ? (wid == 0 ? c4 : c5) : (wid == 2 ? c6 : c7);
                pr = (wid < 2) ? (wid == 0 ? p4 : p5) : (wid == 2 ? p6 : p7);
            }
            if (tp < cr) s_map[pr + tp] = (unsigned char)(q * 128 + threadIdx.x);
        }
    }

    // Weight staging (transpose): s_w[g*10 + h] = W[h*50 + g]
    {
        const float* W = emb + (size_t)b * (NUM_HEADS * NUM_G);
        for (int i = threadIdx.x; i < NUM_HEADS * NUM_G; i += 128) {
            int h = i / NUM_G, g = i - h * NUM_G;
            s_w[g * 10 + h] = __ldg(W + i);
        }
    }
    __syncthreads();                             // the ONLY barrier
    if (threadIdx.x < 2) g_cnt8[2 * b + threadIdx.x] = make_int4(0, 0, 0, 0);

    const int2* bin = &g_bins[b * BINSZ];
    const float K2f = (float)RBF_K;
    const float DLT = (float)RBF_DELTA;

    for (int i0 = threadIdx.x; i0 < cnt; i0 += 128) {
        int2  pe = __ldg(&bin[s_map[i0]]);
        float d  = __int_as_float(pe.y);

        // truncated support: taps gs..gs+11 around g0 = floor(d/delta)
        int g0 = __float2int_rd(d * (float)INV_DELTA);
        int gs = min(max(g0 - 5, 0), GS_MAX);

        unsigned long long acc01 = 0ull, acc23 = 0ull, acc45 = 0ull, acc67 = 0ull;
        float x = d - (float)gs * DLT;
        const float* row = &s_w[gs * 10];

#pragma unroll
        for (int j = 0; j < NTAPS; j++) {
            float r = ex2((K2f * x) * x);
            unsigned long long r2 = pk2(r, r);
            const unsigned long long* w = (const unsigned long long*)row;
            acc01 = fma2(w[0], r2, acc01);
            acc23 = fma2(w[1], r2, acc23);
            acc45 = fma2(w[2], r2, acc45);
            acc67 = fma2(w[3], r2, acc67);
            x -= DLT;
            row += 10;
        }

        float r0, r1, r2f, r3, r4, r5, r6, r7;
        upk2(acc01, r0, r1);
        upk2(acc23, r2f, r3);
        upk2(acc45, r4, r5);
        upk2(acc67, r6, r7);

        float4* o = (float4*)(out + (size_t)pe.x * NUM_HEADS);
        o[0] = make_float4(r0, r1, r2f, r3);
        o[1] = make_float4(r4, r5, r6, r7);
    }
}

extern "C" void kernel_launch(void* const* d_in, const int* in_sizes, int n_in,
                              void* d_out, int out_size)
{
    const int*   anum = (const int*)d_in[0];
    const int*   eidx = (const int*)d_in[1];   // [2, E]
    const float* dist = (const float*)d_in[2];
    const float* emb  = (const float*)d_in[3];
    float*       out  = (float*)d_out;

    int E = in_sizes[2];                       // dist has E elements
    if (E > E_MAX) E = E_MAX;

    int blocks = (E + 256 * 4 - 1) / (256 * 4);
    k_key_direct<<<blocks, 256>>>(anum, eidx, eidx + E, dist, E);
    k_compute<<<NB + 1, 128>>>(anum, eidx, eidx + E, dist, emb, out);
}

// round 16
// speedup vs baseline: 1.0043x; 1.0043x over previous
#include <cuda_runtime.h>
#include <cuda_bf16.h>

// Problem constants
#define NUM_HEADS 8
#define NUM_G     50
#define NUM_ELEM  100
#define NB        (NUM_ELEM * NUM_ELEM)   // 10000 distinct (src,dst) pairs
#define E_MAX     1000000
#define NREP      8                       // counter replicas per bin
#define RCAP      32                      // slots per replica (8*32 = 256 per bin)
#define BINSZ     (NREP * RCAP)           // 256
#define OVF_MAX   8192
#define NTAPS     12                      // truncated RBF support (see analysis)
#define GS_MAX    (NUM_G - NTAPS)         // 38

// offsets = linspace(0, 12, 50) -> spacing 12/49 ; std = 12/50
#define RBF_DELTA (12.0 / 49.0)
#define INV_DELTA (49.0 / 12.0)
// k = -0.5/std^2 * log2(e)  (so exp() becomes ex2.approx)
#define RBF_K     (-8.680555555555555 * 1.4426950408889634)
// arg(g) = K*d^2 + MSLOPE*g*d + CQUAD*g^2   (used by overflow path)
#define MSLOPE    (-2.0 * RBF_K * RBF_DELTA)
#define CQUAD     (RBF_K * RBF_DELTA * RBF_DELTA)

// ---- f32x2 packed helpers (sm_100+ PTX) -----------------------------------
__device__ __forceinline__ unsigned long long pk2(float x, float y) {
    unsigned long long r;
    asm("mov.b64 %0, {%1, %2};" : "=l"(r) : "f"(x), "f"(y));
    return r;
}
__device__ __forceinline__ void upk2(unsigned long long v, float& x, float& y) {
    asm("mov.b64 {%0, %1}, %2;" : "=f"(x), "=f"(y) : "l"(v));
}
__device__ __forceinline__ unsigned long long fma2(unsigned long long a, unsigned long long b,
                                                   unsigned long long c) {
    unsigned long long d;
    asm("fma.rn.f32x2 %0, %1, %2, %3;" : "=l"(d) : "l"(a), "l"(b), "l"(c));
    return d;
}
__device__ __forceinline__ float ex2(float x) {
    float r;
    asm("ex2.approx.f32 %0, %1;" : "=f"(r) : "f"(x));
    return r;
}

// Scratch (no allocations allowed) -------------------------------------------
// g_cnt8 starts zeroed (device global); k_compute re-zeros its bin each launch.
__device__ int4 g_cnt8[NB * 2];            // 8 replica counters per bin
__device__ int2 g_bins[NB * BINSZ];        // {edge_id, dist_bits} (20 MB)
__device__ int  g_ovf_cnt;
__device__ int  g_ovf[OVF_MAX];

// K1: key + replica rank + direct bucket store, software-pipelined MLP=4 ------
// (FROZEN: measured 22.3-22.7us across rounds 11/13/14)
__global__ __launch_bounds__(256) void k_key_direct(
    const int*   __restrict__ anum,
    const int*   __restrict__ esrc,
    const int*   __restrict__ edst,
    const float* __restrict__ dist,
    int E)
{
    const int S   = gridDim.x * blockDim.x;
    const int idx = blockIdx.x * blockDim.x + threadIdx.x;

    int   e[4], s[4], t[4], as[4], ad[4];
    float dd[4];
    bool  ok[4];

#pragma unroll
    for (int u = 0; u < 4; u++) {
        e[u]  = idx + u * S;
        ok[u] = (e[u] < E);
        if (ok[u]) {
            s[u] = __ldg(esrc + e[u]);
            t[u] = __ldg(edst + e[u]);
        }
    }
#pragma unroll
    for (int u = 0; u < 4; u++) {
        if (ok[u]) {
            as[u] = __ldg(anum + s[u]);
            ad[u] = __ldg(anum + t[u]);
            dd[u] = __ldg(dist + e[u]);
        }
    }
    int pos[4], kk[4];
#pragma unroll
    for (int u = 0; u < 4; u++) {
        if (ok[u]) {
            kk[u] = as[u] * NUM_ELEM + ad[u];
            int r = e[u] & (NREP - 1);
            pos[u] = atomicAdd(&((int*)g_cnt8)[kk[u] * NREP + r], 1);
        }
    }
#pragma unroll
    for (int u = 0; u < 4; u++) {
        if (ok[u]) {
            int r = e[u] & (NREP - 1);
            if (pos[u] < RCAP) {
                g_bins[(kk[u] * NREP + r) * RCAP + pos[u]] =
                    make_int2(e[u], __float_as_int(dd[u]));
            } else {
                int o = atomicAdd(&g_ovf_cnt, 1);
                if (o < OVF_MAX) g_ovf[o] = e[u];
            }
        }
    }
}

// K2: one block per pair (+1 overflow block); truncated 12-tap RBF dot.
// Weights transposed in smem: s_w[g*10 + h] (rows padded to 40B for bank spread)
__global__ __launch_bounds__(128) void k_compute(
    const int*   __restrict__ anum,
    const int*   __restrict__ esrc,
    const int*   __restrict__ edst,
    const float* __restrict__ dist,
    const float* __restrict__ emb,
    float*       __restrict__ out)
{
    int b = blockIdx.x;                          // pair key

    // --- overflow block (normally empty); exact 50-tap path ------------------
    if (b == NB) {
        int n = g_ovf_cnt;
        if (n > OVF_MAX) n = OVF_MAX;
        for (int i = threadIdx.x; i < n; i += 128) {
            int e = g_ovf[i];
            int k = __ldg(anum + __ldg(esrc + e)) * NUM_ELEM
                  + __ldg(anum + __ldg(edst + e));
            float d = __ldg(dist + e);
            const float* W = emb + (size_t)k * (NUM_HEADS * NUM_G);
            float t = (float)RBF_K * d * d;
            float rbf[NUM_G];
#pragma unroll
            for (int g = 0; g < NUM_G; g++)
                rbf[g] = ex2(t + (float)(MSLOPE * g) * d + (float)(CQUAD * g * g));
            for (int h = 0; h < NUM_HEADS; h++) {
                float a = 0.f;
#pragma unroll
                for (int g = 0; g < NUM_G; g++)
                    a = fmaf(__ldg(W + h * NUM_G + g), rbf[g], a);
                out[(size_t)e * NUM_HEADS + h] = a;
            }
        }
        __syncthreads();
        if (threadIdx.x == 0) g_ovf_cnt = 0;     // reset for next launch/replay
        return;
    }

    // --- normal bin block ----------------------------------------------------
    __shared__ unsigned char s_map[BINSZ];            // logical idx -> bin slot
    __shared__ __align__(16) float s_w[NUM_G * 10];   // [g][h] rows padded to 10

    // Broadcast counter loads (all threads)
    int4 ca = g_cnt8[2 * b];
    int4 cb = g_cnt8[2 * b + 1];
    int c0 = min(ca.x, RCAP), c1 = min(ca.y, RCAP);
    int c2 = min(ca.z, RCAP), c3 = min(ca.w, RCAP);
    int c4 = min(cb.x, RCAP), c5 = min(cb.y, RCAP);
    int c6 = min(cb.z, RCAP), c7 = min(cb.w, RCAP);
    int p0 = 0;
    int p1 = p0 + c0, p2 = p1 + c1, p3 = p2 + c2, p4 = p3 + c3;
    int p5 = p4 + c4, p6 = p5 + c5, p7 = p6 + c6;
    int cnt = p7 + c7;
    if (cnt == 0) return;                        // uniform: whole block exits

    // Build logical->slot map: slot idx = q*128+tid, replica = q*4 + (tid>>5)
    {
        int wid = threadIdx.x >> 5;
        int tp  = threadIdx.x & (RCAP - 1);
#pragma unroll
        for (int q = 0; q < 2; q++) {
            int cr, pr;
            if (q == 0) {
                cr = (wid < 2) ? (wid == 0 ? c0 : c1) : (wid == 2 ? c2 : c3);
                pr = (wid < 2) ? (wid == 0 ? p0 : p1) : (wid == 2 ? p2 : p3);
            } else {
                cr = (wid < 2) ? (wid == 0 ? c4 : c5) : (wid == 2 ? c6 : c7);
                pr = (wid < 2) ? (wid == 0 ? p4 : p5) : (wid == 2 ? p6 : p7);
            }
            if (tp < cr) s_map[pr + tp] = (unsigned char)(q * 128 + threadIdx.x);
        }
    }

    // Weight staging (transpose): s_w[g*10 + h] = W[h*50 + g]
    {
        const float* W = emb + (size_t)b * (NUM_HEADS * NUM_G);
        for (int i = threadIdx.x; i < NUM_HEADS * NUM_G; i += 128) {
            int h = i / NUM_G, g = i - h * NUM_G;
            s_w[g * 10 + h] = __ldg(W + i);
        }
    }
    __syncthreads();                             // the ONLY barrier
    if (threadIdx.x < 2) g_cnt8[2 * b + threadIdx.x] = make_int4(0, 0, 0, 0);

    const int2* bin = &g_bins[b * BINSZ];
    const float K2f = (float)RBF_K;
    const float DLT = (float)RBF_DELTA;

    for (int i0 = threadIdx.x; i0 < cnt; i0 += 128) {
        int2  pe = __ldg(&bin[s_map[i0]]);
        float d  = __int_as_float(pe.y);

        // truncated support: taps gs..gs+11 around g0 = floor(d/delta)
        int g0 = __float2int_rd(d * (float)INV_DELTA);
        int gs = min(max(g0 - 5, 0), GS_MAX);

        unsigned long long acc01 = 0ull, acc23 = 0ull, acc45 = 0ull, acc67 = 0ull;
        float x = d - (float)gs * DLT;
        const float* row = &s_w[gs * 10];

#pragma unroll
        for (int j = 0; j < NTAPS; j++) {
            float r = ex2((K2f * x) * x);
            unsigned long long r2 = pk2(r, r);
            const unsigned long long* w = (const unsigned long long*)row;
            acc01 = fma2(w[0], r2, acc01);
            acc23 = fma2(w[1], r2, acc23);
            acc45 = fma2(w[2], r2, acc45);
            acc67 = fma2(w[3], r2, acc67);
            x -= DLT;
            row += 10;
        }

        float r0, r1, r2f, r3, r4, r5, r6, r7;
        upk2(acc01, r0, r1);
        upk2(acc23, r2f, r3);
        upk2(acc45, r4, r5);
        upk2(acc67, r6, r7);

        float4* o = (float4*)(out + (size_t)pe.x * NUM_HEADS);
        o[0] = make_float4(r0, r1, r2f, r3);
        o[1] = make_float4(r4, r5, r6, r7);
    }
}

extern "C" void kernel_launch(void* const* d_in, const int* in_sizes, int n_in,
                              void* d_out, int out_size)
{
    const int*   anum = (const int*)d_in[0];
    const int*   eidx = (const int*)d_in[1];   // [2, E]
    const float* dist = (const float*)d_in[2];
    const float* emb  = (const float*)d_in[3];
    float*       out  = (float*)d_out;

    int E = in_sizes[2];                       // dist has E elements
    if (E > E_MAX) E = E_MAX;

    int blocks = (E + 256 * 4 - 1) / (256 * 4);
    k_key_direct<<<blocks, 256>>>(anum, eidx, eidx + E, dist, E);
    k_compute<<<NB + 1, 128>>>(anum, eidx, eidx + E, dist, emb, out);
}